// round 6
// baseline (speedup 1.0000x reference)
#include <cuda_runtime.h>

// Problem constants
#define T_STEPS 256
#define I1 38
#define H1 50
#define H2 15
#define NC 14
#define K1 (I1 + H1)    // 88
#define KSPLIT 44       // k per half-thread in phase 1
#define K2 (H1 + H2)    // 65
#define BT 16
#define AST 20          // activation row stride (floats); 80B rows
#define NTHREADS 512
#define NBLOCKS 256

// Shared layout (floats):
//  W1s [K1][H1][4]  17600   (k, unit, gate i/f/g/o)
//  W2s [K2][H2][4]   3900
//  b1v [H1][4]        200
//  b2v [H2][4]         60
//  wfcs[NC*H2]        210
//  bfcs[NC]            14
//  a1  [2][K1][AST]  3520   rows 0..I1-1 = x_t, rows I1.. = h1
//  a2  [2][H2][AST]   600   h2 only
#define OFF_W1   0
#define OFF_W2   (OFF_W1 + K1 * H1 * 4)
#define OFF_B1   (OFF_W2 + K2 * H2 * 4)
#define OFF_B2   (OFF_B1 + H1 * 4)
#define OFF_WFC  (OFF_B2 + H2 * 4)
#define OFF_BFC  (OFF_WFC + NC * H2)
#define OFF_A1   (OFF_BFC + NC)
#define OFF_A2   (OFF_A1 + 2 * K1 * AST)
#define SMEM_FLOATS (OFF_A2 + 2 * H2 * AST)
#define SMEM_BYTES (SMEM_FLOATS * 4)   // ~106.5 KB -> 2 blocks/SM

__device__ __forceinline__ float fsig(float x) {
    return __fdividef(1.0f, 1.0f + __expf(-x));
}
__device__ __forceinline__ float ftanh_fast(float x) {
    return 1.0f - __fdividef(2.0f, 1.0f + __expf(2.0f * x));
}

__device__ __forceinline__ unsigned long long pack2(float w) {
    unsigned long long r;
    asm("mov.b64 %0, {%1, %1};" : "=l"(r) : "f"(w));
    return r;
}
__device__ __forceinline__ unsigned long long packf2(float a, float b) {
    unsigned long long r;
    asm("mov.b64 %0, {%1, %2};" : "=l"(r) : "f"(a), "f"(b));
    return r;
}
__device__ __forceinline__ void ffma2(unsigned long long& d,
                                      unsigned long long a, unsigned long long b) {
    asm("fma.rn.f32x2 %0, %1, %2, %0;" : "+l"(d) : "l"(a), "l"(b));
}
__device__ __forceinline__ unsigned long long fadd2(unsigned long long a,
                                                    unsigned long long b) {
    unsigned long long r;
    asm("add.rn.f32x2 %0, %1, %2;" : "=l"(r) : "l"(a), "l"(b));
    return r;
}
__device__ __forceinline__ float2 unpk2(unsigned long long v) {
    float2 r;
    asm("mov.b64 {%0, %1}, %2;" : "=f"(r.x), "=f"(r.y) : "l"(v));
    return r;
}

extern __shared__ float smem[];

__global__ __launch_bounds__(NTHREADS, 2)
void lstm2_fused_kernel(const float* __restrict__ x,
                        const float* __restrict__ w_ih1, const float* __restrict__ w_hh1,
                        const float* __restrict__ b_ih1, const float* __restrict__ b_hh1,
                        const float* __restrict__ w_ih2, const float* __restrict__ w_hh2,
                        const float* __restrict__ b_ih2, const float* __restrict__ b_hh2,
                        const float* __restrict__ w_fc, const float* __restrict__ b_fc,
                        float* __restrict__ out)
{
    float* W1s  = smem + OFF_W1;
    float* W2s  = smem + OFF_W2;
    float* b1v  = smem + OFF_B1;
    float* b2v  = smem + OFF_B2;
    float* wfcs = smem + OFF_WFC;
    float* bfcs = smem + OFF_BFC;
    float* a1   = smem + OFF_A1;
    float* a2   = smem + OFF_A2;

    const int tid = threadIdx.x;
    const int b0  = blockIdx.x * BT;

    // ---- stage weights: (k, unit, gate) float4 groups ----
    for (int i = tid; i < K1 * H1 * 4; i += NTHREADS) {
        int k = i / (H1 * 4);
        int r = i - k * (H1 * 4);
        int uu = r >> 2, gi = r & 3;
        W1s[i] = (k < I1) ? w_ih1[(gi * H1 + uu) * I1 + k]
                          : w_hh1[(gi * H1 + uu) * H1 + (k - I1)];
    }
    for (int i = tid; i < K2 * H2 * 4; i += NTHREADS) {
        int k = i / (H2 * 4);
        int r = i - k * (H2 * 4);
        int uu = r >> 2, gi = r & 3;
        W2s[i] = (k < H1) ? w_ih2[(gi * H2 + uu) * H1 + k]
                          : w_hh2[(gi * H2 + uu) * H2 + (k - H1)];
    }
    for (int i = tid; i < H1 * 4; i += NTHREADS) {
        int uu = i >> 2, gi = i & 3;
        b1v[i] = b_ih1[gi * H1 + uu] + b_hh1[gi * H1 + uu];
    }
    for (int i = tid; i < H2 * 4; i += NTHREADS) {
        int uu = i >> 2, gi = i & 3;
        b2v[i] = b_ih2[gi * H2 + uu] + b_hh2[gi * H2 + uu];
    }
    for (int i = tid; i < NC * H2; i += NTHREADS) wfcs[i] = w_fc[i];
    for (int i = tid; i < NC; i += NTHREADS) bfcs[i] = b_fc[i];

    // ---- zero initial states (buffer 0); load x_0 ----
    for (int i = tid; i < H1 * AST; i += NTHREADS) a1[I1 * AST + i] = 0.0f;
    for (int i = tid; i < H2 * AST; i += NTHREADS) a2[i] = 0.0f;
    for (int i = tid; i < BT * I1; i += NTHREADS) {
        int b = i / I1, k = i % I1;
        a1[k * AST + b] = x[(size_t)(b0 + b) * (T_STEPS * I1) + k];
    }

    // ---- thread role assignment ----
    // Phase 1: tids 0..399. Lane pairs split the k loop.
    //   r = tid>>1: u = r%50, quad = r/50 ; half = tid&1 (k in [half*44, half*44+44))
    const bool is_p1 = (tid < 400);
    const int r1   = tid >> 1;
    const int u    = r1 % 50;
    const int quad = r1 / 50;       // 0..3 (4 batches each, pair handles 2 each)
    const int half = tid & 1;
    const unsigned p1mask = __ballot_sync(0xffffffffu, is_p1);

    // Phase 2: tids 416..475 (60): unit u2, gate-pair gp, octet oct2
    const bool is_p2 = (tid >= 416) && (tid < 476);
    const int j2   = tid - 416;
    const int gp   = j2 & 1;        // 0: gates i,f ; 1: gates g,o
    const int rst  = j2 >> 1;       // 0..29
    const int u2   = rst % 15;
    const int oct2 = rst / 15;      // 0..1 (8 batches each)
    const unsigned p2mask = __ballot_sync(0xffffffffu, is_p2);

    float c1r[2] = {0.f, 0.f};      // this lane's 2 batches: quad*4 + half*2 + {0,1}
    float c2r[4] = {0.f, 0.f, 0.f, 0.f};

    __syncthreads();

    for (int t = 0; t < T_STEPS; ++t) {
        const int p = t & 1, q = p ^ 1;
        float* a1p = a1 + p * (K1 * AST);
        float* a1q = a1 + q * (K1 * AST);
        float* a2p = a2 + p * (H2 * AST);
        float* a2q = a2 + q * (H2 * AST);

        // ===== Phase 1: 400 threads, lane-pair k-split, 1u x 4g x 4b per pair =====
        if (is_p1) {
            unsigned long long acc[4][2];
            if (half == 0) {
                float4 bv = *reinterpret_cast<const float4*>(b1v + u * 4);
                acc[0][0] = acc[0][1] = pack2(bv.x);
                acc[1][0] = acc[1][1] = pack2(bv.y);
                acc[2][0] = acc[2][1] = pack2(bv.z);
                acc[3][0] = acc[3][1] = pack2(bv.w);
            } else {
                acc[0][0] = acc[0][1] = 0ull;
                acc[1][0] = acc[1][1] = 0ull;
                acc[2][0] = acc[2][1] = 0ull;
                acc[3][0] = acc[3][1] = 0ull;
            }
            const float4* wp = reinterpret_cast<const float4*>(W1s)
                               + half * (KSPLIT * H1) + u;
            const char* ap = reinterpret_cast<const char*>(a1p)
                             + half * (KSPLIT * AST * 4) + 16 * quad;
            #pragma unroll 4
            for (int k = 0; k < KSPLIT; ++k) {
                float4 wv = *wp; wp += H1;
                ulonglong2 av = *reinterpret_cast<const ulonglong2*>(ap);
                ap += AST * 4;
                unsigned long long w0 = pack2(wv.x);
                unsigned long long w1 = pack2(wv.y);
                unsigned long long w2 = pack2(wv.z);
                unsigned long long w3 = pack2(wv.w);
                ffma2(acc[0][0], w0, av.x); ffma2(acc[0][1], w0, av.y);
                ffma2(acc[1][0], w1, av.x); ffma2(acc[1][1], w1, av.y);
                ffma2(acc[2][0], w2, av.x); ffma2(acc[2][1], w2, av.y);
                ffma2(acc[3][0], w3, av.x); ffma2(acc[3][1], w3, av.y);
            }
            // pair-merge: each lane keeps batch-pair == half, sends the other
            unsigned long long full[4];
            #pragma unroll
            for (int gi = 0; gi < 4; ++gi) {
                unsigned long long sendv = half ? acc[gi][0] : acc[gi][1];
                unsigned long long recvv = __shfl_xor_sync(p1mask, sendv, 1);
                full[gi] = fadd2(half ? acc[gi][1] : acc[gi][0], recvv);
            }
            float2 vi = unpk2(full[0]);
            float2 vf = unpk2(full[1]);
            float2 vg = unpk2(full[2]);
            float2 vo = unpk2(full[3]);
            float hv[2];
            #pragma unroll
            for (int l = 0; l < 2; ++l) {
                float ig = fsig(l ? vi.y : vi.x);
                float fg = fsig(l ? vf.y : vf.x);
                float gg = ftanh_fast(l ? vg.y : vg.x);
                float og = fsig(l ? vo.y : vo.x);
                float c  = fg * c1r[l] + ig * gg;
                c1r[l]   = c;
                hv[l]    = og * ftanh_fast(c);
            }
            *reinterpret_cast<unsigned long long*>(
                a1q + (I1 + u) * AST + 4 * quad + 2 * half) = packf2(hv[0], hv[1]);
        } else if (tid >= 476) {
            // tids 476..511: prefetch x_{t+1}
            if (t + 1 < T_STEPS) {
                for (int i = tid - 476; i < BT * I1; i += (NTHREADS - 476)) {
                    int b = i / I1, k = i % I1;
                    a1q[k * AST + b] =
                        x[(size_t)(b0 + b) * (T_STEPS * I1) + (size_t)(t + 1) * I1 + k];
                }
            }
        }

        __syncthreads();   // the ONLY barrier per step

        // ===== Phase 2: layer-2, 60 threads (warps 13-14), 1u x 2g x 8b each =====
        // reads h1 directly from a1q h-rows (written this step), h2 from a2p
        if (is_p2) {
            unsigned long long P[4], Q[4];   // gp0: P=i,Q=f ; gp1: P=g,Q=o
            {
                float2 bb = *reinterpret_cast<const float2*>(b2v + u2 * 4 + gp * 2);
                unsigned long long bl = pack2(bb.x), bh = pack2(bb.y);
                #pragma unroll
                for (int bp = 0; bp < 4; ++bp) { P[bp] = bl; Q[bp] = bh; }
            }
            const unsigned long long* wp2 =
                reinterpret_cast<const unsigned long long*>(W2s) + u2 * 2 + gp;
            const char* ah = reinterpret_cast<const char*>(a1q + I1 * AST) + 32 * oct2; // h1 new
            #pragma unroll 5
            for (int k = 0; k < H1; ++k) {
                float2 wv = unpk2(*wp2); wp2 += H2 * 2;
                ulonglong2 aL = *reinterpret_cast<const ulonglong2*>(ah);
                ulonglong2 aH = *reinterpret_cast<const ulonglong2*>(ah + 16);
                ah += AST * 4;
                unsigned long long wl = pack2(wv.x), wh = pack2(wv.y);
                ffma2(P[0], wl, aL.x); ffma2(P[1], wl, aL.y);
                ffma2(P[2], wl, aH.x); ffma2(P[3], wl, aH.y);
                ffma2(Q[0], wh, aL.x); ffma2(Q[1], wh, aL.y);
                ffma2(Q[2], wh, aH.x); ffma2(Q[3], wh, aH.y);
            }
            const char* ah2 = reinterpret_cast<const char*>(a2p) + 32 * oct2;  // h2 old
            #pragma unroll
            for (int k = 0; k < H2; ++k) {
                float2 wv = unpk2(*wp2); wp2 += H2 * 2;
                ulonglong2 aL = *reinterpret_cast<const ulonglong2*>(ah2);
                ulonglong2 aH = *reinterpret_cast<const ulonglong2*>(ah2 + 16);
                ah2 += AST * 4;
                unsigned long long wl = pack2(wv.x), wh = pack2(wv.y);
                ffma2(P[0], wl, aL.x); ffma2(P[1], wl, aL.y);
                ffma2(P[2], wl, aH.x); ffma2(P[3], wl, aH.y);
                ffma2(Q[0], wh, aL.x); ffma2(Q[1], wh, aL.y);
                ffma2(Q[2], wh, aH.x); ffma2(Q[3], wh, aH.y);
            }
            // lane-pair exchange: even lane (gp0) keeps batch-pairs 0,1; odd keeps 2,3
            const bool evn = (gp == 0);
            unsigned long long GI[2], GF[2], GG[2], GO[2];
            #pragma unroll
            for (int jj = 0; jj < 2; ++jj) {
                unsigned long long sP = evn ? P[2 + jj] : P[jj];
                unsigned long long sQ = evn ? Q[2 + jj] : Q[jj];
                unsigned long long rP = __shfl_xor_sync(p2mask, sP, 1);
                unsigned long long rQ = __shfl_xor_sync(p2mask, sQ, 1);
                GI[jj] = evn ? P[jj]     : rP;
                GF[jj] = evn ? Q[jj]     : rQ;
                GG[jj] = evn ? rP        : P[2 + jj];
                GO[jj] = evn ? rQ        : Q[2 + jj];
            }
            float hv[4];
            #pragma unroll
            for (int jj = 0; jj < 2; ++jj) {
                float2 vi = unpk2(GI[jj]);
                float2 vf = unpk2(GF[jj]);
                float2 vg = unpk2(GG[jj]);
                float2 vo = unpk2(GO[jj]);
                #pragma unroll
                for (int l = 0; l < 2; ++l) {
                    int bj = 2 * jj + l;
                    float ig = fsig(l ? vi.y : vi.x);
                    float fg = fsig(l ? vf.y : vf.x);
                    float gg = ftanh_fast(l ? vg.y : vg.x);
                    float og = fsig(l ? vo.y : vo.x);
                    float c  = fg * c2r[bj] + ig * gg;
                    c2r[bj]  = c;
                    hv[bj]   = og * ftanh_fast(c);
                }
            }
            float* d = a2q + u2 * AST + oct2 * 8 + gp * 4;
            *reinterpret_cast<float4*>(d) = make_float4(hv[0], hv[1], hv[2], hv[3]);
        }
        // no barrier: next phase-1 touches disjoint rows/buffers
    }

    __syncthreads();
    // final h2 in buffer q of step 255: q = 0
    if (tid < BT * NC) {
        int b = tid / NC, n = tid % NC;
        const float* h2f = a2;   // buffer 0
        float s = bfcs[n];
        #pragma unroll
        for (int j = 0; j < H2; ++j)
            s += h2f[j * AST + b] * wfcs[n * H2 + j];
        out[(size_t)(b0 + b) * NC + n] = s;
    }
}

extern "C" void kernel_launch(void* const* d_in, const int* in_sizes, int n_in,
                              void* d_out, int out_size)
{
    (void)in_sizes; (void)n_in; (void)out_size;
    const float* x     = (const float*)d_in[0];
    const float* w_ih1 = (const float*)d_in[1];
    const float* w_hh1 = (const float*)d_in[2];
    const float* b_ih1 = (const float*)d_in[3];
    const float* b_hh1 = (const float*)d_in[4];
    const float* w_ih2 = (const float*)d_in[5];
    const float* w_hh2 = (const float*)d_in[6];
    const float* b_ih2 = (const float*)d_in[7];
    const float* b_hh2 = (const float*)d_in[8];
    const float* w_fc  = (const float*)d_in[9];
    const float* b_fc  = (const float*)d_in[10];
    float* out = (float*)d_out;

    cudaFuncSetAttribute(lstm2_fused_kernel,
                         cudaFuncAttributeMaxDynamicSharedMemorySize, SMEM_BYTES);

    lstm2_fused_kernel<<<NBLOCKS, NTHREADS, SMEM_BYTES>>>(
        x, w_ih1, w_hh1, b_ih1, b_hh1,
        w_ih2, w_hh2, b_ih2, b_hh2,
        w_fc, b_fc, out);
}

// round 7
// speedup vs baseline: 1.3847x; 1.3847x over previous
#include <cuda_runtime.h>

// Problem constants
#define T_STEPS 256
#define I1 38
#define H1 50
#define H2 15
#define NC 14
#define K1 (I1 + H1)    // 88
#define K2 (H1 + H2)    // 65
#define BT 16
#define AST 20          // activation row stride (floats); 80B rows
#define NTHREADS 384
#define NBLOCKS 256

// Shared layout (floats):
//  W1s [K1][H1][4]  17600   (k, unit, gate i/f/g/o)
//  W2s [K2][H2][4]   3900
//  b1v [H1][4]        200
//  b2v [H2][4]         60
//  wfcs[NC*H2]        210
//  bfcs[NC]            14
//  a1  [2][K1][AST]  3520   rows 0..I1-1 = x_t, rows I1.. = h1
//  a2  [2][H2][AST]   600   h2 only
#define OFF_W1   0
#define OFF_W2   (OFF_W1 + K1 * H1 * 4)
#define OFF_B1   (OFF_W2 + K2 * H2 * 4)
#define OFF_B2   (OFF_B1 + H1 * 4)
#define OFF_WFC  (OFF_B2 + H2 * 4)
#define OFF_BFC  (OFF_WFC + NC * H2)
#define OFF_A1   (OFF_BFC + NC)
#define OFF_A2   (OFF_A1 + 2 * K1 * AST)
#define SMEM_FLOATS (OFF_A2 + 2 * H2 * AST)
#define SMEM_BYTES (SMEM_FLOATS * 4)   // ~106.5 KB -> 2 blocks/SM

__device__ __forceinline__ float fsig(float x) {
    return __fdividef(1.0f, 1.0f + __expf(-x));
}
__device__ __forceinline__ float ftanh_fast(float x) {
    return 1.0f - __fdividef(2.0f, 1.0f + __expf(2.0f * x));
}

__device__ __forceinline__ unsigned long long pack2(float w) {
    unsigned long long r;
    asm("mov.b64 %0, {%1, %1};" : "=l"(r) : "f"(w));
    return r;
}
__device__ __forceinline__ void ffma2(unsigned long long& d,
                                      unsigned long long a, unsigned long long b) {
    asm("fma.rn.f32x2 %0, %1, %2, %0;" : "+l"(d) : "l"(a), "l"(b));
}
__device__ __forceinline__ float2 unpk2(unsigned long long v) {
    float2 r;
    asm("mov.b64 {%0, %1}, %2;" : "=f"(r.x), "=f"(r.y) : "l"(v));
    return r;
}

extern __shared__ float smem[];

__global__ __launch_bounds__(NTHREADS, 2)
void lstm2_fused_kernel(const float* __restrict__ x,
                        const float* __restrict__ w_ih1, const float* __restrict__ w_hh1,
                        const float* __restrict__ b_ih1, const float* __restrict__ b_hh1,
                        const float* __restrict__ w_ih2, const float* __restrict__ w_hh2,
                        const float* __restrict__ b_ih2, const float* __restrict__ b_hh2,
                        const float* __restrict__ w_fc, const float* __restrict__ b_fc,
                        float* __restrict__ out)
{
    float* W1s  = smem + OFF_W1;
    float* W2s  = smem + OFF_W2;
    float* b1v  = smem + OFF_B1;
    float* b2v  = smem + OFF_B2;
    float* wfcs = smem + OFF_WFC;
    float* bfcs = smem + OFF_BFC;
    float* a1   = smem + OFF_A1;
    float* a2   = smem + OFF_A2;

    const int tid = threadIdx.x;
    const int b0  = blockIdx.x * BT;

    // ---- stage weights: (k, unit, gate) float4 groups ----
    for (int i = tid; i < K1 * H1 * 4; i += NTHREADS) {
        int k = i / (H1 * 4);
        int r = i - k * (H1 * 4);
        int uu = r >> 2, gi = r & 3;
        W1s[i] = (k < I1) ? w_ih1[(gi * H1 + uu) * I1 + k]
                          : w_hh1[(gi * H1 + uu) * H1 + (k - I1)];
    }
    for (int i = tid; i < K2 * H2 * 4; i += NTHREADS) {
        int k = i / (H2 * 4);
        int r = i - k * (H2 * 4);
        int uu = r >> 2, gi = r & 3;
        W2s[i] = (k < H1) ? w_ih2[(gi * H2 + uu) * H1 + k]
                          : w_hh2[(gi * H2 + uu) * H2 + (k - H1)];
    }
    for (int i = tid; i < H1 * 4; i += NTHREADS) {
        int uu = i >> 2, gi = i & 3;
        b1v[i] = b_ih1[gi * H1 + uu] + b_hh1[gi * H1 + uu];
    }
    for (int i = tid; i < H2 * 4; i += NTHREADS) {
        int uu = i >> 2, gi = i & 3;
        b2v[i] = b_ih2[gi * H2 + uu] + b_hh2[gi * H2 + uu];
    }
    for (int i = tid; i < NC * H2; i += NTHREADS) wfcs[i] = w_fc[i];
    for (int i = tid; i < NC; i += NTHREADS) bfcs[i] = b_fc[i];

    // ---- zero initial states (buffer 0); load x_0 ----
    for (int i = tid; i < H1 * AST; i += NTHREADS) a1[I1 * AST + i] = 0.0f;
    for (int i = tid; i < H2 * AST; i += NTHREADS) a2[i] = 0.0f;
    for (int i = tid; i < BT * I1; i += NTHREADS) {
        int b = i / I1, k = i % I1;
        a1[k * AST + b] = x[(size_t)(b0 + b) * (T_STEPS * I1) + k];
    }

    // ---- thread role assignment ----
    // Phase 1: tids 0..199 (dense). DEDUP MAPPING: lanes 0-3 share one unit.
    //   u = tid>>2 (0..49), quad = tid&3 -> warp's weight reads hit 8 distinct
    //   consecutive float4s (128B, broadcast x4) instead of 32 distinct ones.
    const bool is_p1 = (tid < 200);
    const int u    = tid >> 2;
    const int quad = tid & 3;       // 0..3 (4 batches each)

    // Phase 2: tids 224..283 (60): unit u2, gate-pair gp, octet oct2
    const bool is_p2 = (tid >= 224) && (tid < 284);
    const int j2   = tid - 224;
    const int gp   = j2 & 1;        // 0: gates i,f ; 1: gates g,o
    const int rst  = j2 >> 1;       // 0..29
    const int u2   = rst % 15;
    const int oct2 = rst / 15;      // 0..1 (8 batches each)
    const unsigned p2mask = __ballot_sync(0xffffffffu, is_p2);

    float c1r[4] = {0.f,0.f,0.f,0.f};
    float c2r[4] = {0.f,0.f,0.f,0.f};

    __syncthreads();

    for (int t = 0; t < T_STEPS; ++t) {
        const int p = t & 1, q = p ^ 1;
        float* a1p = a1 + p * (K1 * AST);
        float* a1q = a1 + q * (K1 * AST);
        float* a2p = a2 + p * (H2 * AST);
        float* a2q = a2 + q * (H2 * AST);

        // ===== Phase 1: layer-1, 200 dense threads, 1u x 4g x 4b each =====
        if (is_p1) {
            unsigned long long acc[4][2];
            {
                float4 bv = *reinterpret_cast<const float4*>(b1v + u * 4);
                acc[0][0] = acc[0][1] = pack2(bv.x);
                acc[1][0] = acc[1][1] = pack2(bv.y);
                acc[2][0] = acc[2][1] = pack2(bv.z);
                acc[3][0] = acc[3][1] = pack2(bv.w);
            }
            const float4* wp = reinterpret_cast<const float4*>(W1s) + u;
            const char* ap = reinterpret_cast<const char*>(a1p) + 16 * quad;
            #pragma unroll 4
            for (int k = 0; k < K1; ++k) {
                float4 wv = *wp; wp += H1;
                ulonglong2 av = *reinterpret_cast<const ulonglong2*>(ap);
                ap += AST * 4;
                unsigned long long w0 = pack2(wv.x);
                unsigned long long w1 = pack2(wv.y);
                unsigned long long w2 = pack2(wv.z);
                unsigned long long w3 = pack2(wv.w);
                ffma2(acc[0][0], w0, av.x); ffma2(acc[0][1], w0, av.y);
                ffma2(acc[1][0], w1, av.x); ffma2(acc[1][1], w1, av.y);
                ffma2(acc[2][0], w2, av.x); ffma2(acc[2][1], w2, av.y);
                ffma2(acc[3][0], w3, av.x); ffma2(acc[3][1], w3, av.y);
            }
            float hv[4];
            #pragma unroll
            for (int bp = 0; bp < 2; ++bp) {
                float2 vi = unpk2(acc[0][bp]);
                float2 vf = unpk2(acc[1][bp]);
                float2 vg = unpk2(acc[2][bp]);
                float2 vo = unpk2(acc[3][bp]);
                #pragma unroll
                for (int l = 0; l < 2; ++l) {
                    int bj = 2 * bp + l;
                    float ig = fsig(l ? vi.y : vi.x);
                    float fg = fsig(l ? vf.y : vf.x);
                    float gg = ftanh_fast(l ? vg.y : vg.x);
                    float og = fsig(l ? vo.y : vo.x);
                    float c  = fg * c1r[bj] + ig * gg;
                    c1r[bj]  = c;
                    hv[bj]   = og * ftanh_fast(c);
                }
            }
            *reinterpret_cast<float4*>(a1q + (I1 + u) * AST + 4 * quad) =
                make_float4(hv[0], hv[1], hv[2], hv[3]);
        } else if (tid >= 288) {
            // warps 9-11: prefetch x_{t+1}
            if (t + 1 < T_STEPS) {
                for (int i = tid - 288; i < BT * I1; i += (NTHREADS - 288)) {
                    int b = i / I1, k = i % I1;
                    a1q[k * AST + b] =
                        x[(size_t)(b0 + b) * (T_STEPS * I1) + (size_t)(t + 1) * I1 + k];
                }
            }
        }

        __syncthreads();   // the ONLY barrier per step

        // ===== Phase 2: layer-2, 60 threads (warps 7-8), 1u x 2g x 8b each =====
        // reads h1 directly from a1q h-rows (written this step), h2 from a2p
        if (is_p2) {
            unsigned long long P[4], Q[4];   // gp0: P=i,Q=f ; gp1: P=g,Q=o
            {
                float2 bb = *reinterpret_cast<const float2*>(b2v + u2 * 4 + gp * 2);
                unsigned long long bl = pack2(bb.x), bh = pack2(bb.y);
                #pragma unroll
                for (int bp = 0; bp < 4; ++bp) { P[bp] = bl; Q[bp] = bh; }
            }
            const unsigned long long* wp2 =
                reinterpret_cast<const unsigned long long*>(W2s) + u2 * 2 + gp;
            const char* ah = reinterpret_cast<const char*>(a1q + I1 * AST) + 32 * oct2; // h1 new
            #pragma unroll 5
            for (int k = 0; k < H1; ++k) {
                float2 wv = unpk2(*wp2); wp2 += H2 * 2;
                ulonglong2 aL = *reinterpret_cast<const ulonglong2*>(ah);
                ulonglong2 aH = *reinterpret_cast<const ulonglong2*>(ah + 16);
                ah += AST * 4;
                unsigned long long wl = pack2(wv.x), wh = pack2(wv.y);
                ffma2(P[0], wl, aL.x); ffma2(P[1], wl, aL.y);
                ffma2(P[2], wl, aH.x); ffma2(P[3], wl, aH.y);
                ffma2(Q[0], wh, aL.x); ffma2(Q[1], wh, aL.y);
                ffma2(Q[2], wh, aH.x); ffma2(Q[3], wh, aH.y);
            }
            const char* ah2 = reinterpret_cast<const char*>(a2p) + 32 * oct2;  // h2 old
            #pragma unroll
            for (int k = 0; k < H2; ++k) {
                float2 wv = unpk2(*wp2); wp2 += H2 * 2;
                ulonglong2 aL = *reinterpret_cast<const ulonglong2*>(ah2);
                ulonglong2 aH = *reinterpret_cast<const ulonglong2*>(ah2 + 16);
                ah2 += AST * 4;
                unsigned long long wl = pack2(wv.x), wh = pack2(wv.y);
                ffma2(P[0], wl, aL.x); ffma2(P[1], wl, aL.y);
                ffma2(P[2], wl, aH.x); ffma2(P[3], wl, aH.y);
                ffma2(Q[0], wh, aL.x); ffma2(Q[1], wh, aL.y);
                ffma2(Q[2], wh, aH.x); ffma2(Q[3], wh, aH.y);
            }
            // lane-pair exchange: even lane (gp0) keeps batch-pairs 0,1; odd keeps 2,3
            const bool evn = (gp == 0);
            unsigned long long GI[2], GF[2], GG[2], GO[2];
            #pragma unroll
            for (int jj = 0; jj < 2; ++jj) {
                unsigned long long sP = evn ? P[2 + jj] : P[jj];
                unsigned long long sQ = evn ? Q[2 + jj] : Q[jj];
                unsigned long long rP = __shfl_xor_sync(p2mask, sP, 1);
                unsigned long long rQ = __shfl_xor_sync(p2mask, sQ, 1);
                GI[jj] = evn ? P[jj]     : rP;
                GF[jj] = evn ? Q[jj]     : rQ;
                GG[jj] = evn ? rP        : P[2 + jj];
                GO[jj] = evn ? rQ        : Q[2 + jj];
            }
            float hv[4];
            #pragma unroll
            for (int jj = 0; jj < 2; ++jj) {
                float2 vi = unpk2(GI[jj]);
                float2 vf = unpk2(GF[jj]);
                float2 vg = unpk2(GG[jj]);
                float2 vo = unpk2(GO[jj]);
                #pragma unroll
                for (int l = 0; l < 2; ++l) {
                    int bj = 2 * jj + l;
                    float ig = fsig(l ? vi.y : vi.x);
                    float fg = fsig(l ? vf.y : vf.x);
                    float gg = ftanh_fast(l ? vg.y : vg.x);
                    float og = fsig(l ? vo.y : vo.x);
                    float c  = fg * c2r[bj] + ig * gg;
                    c2r[bj]  = c;
                    hv[bj]   = og * ftanh_fast(c);
                }
            }
            float* d = a2q + u2 * AST + oct2 * 8 + gp * 4;
            *reinterpret_cast<float4*>(d) = make_float4(hv[0], hv[1], hv[2], hv[3]);
        }
        // no barrier: next phase-1 touches disjoint rows/buffers
    }

    __syncthreads();
    // final h2 in buffer q of step 255: q = 0
    if (tid < BT * NC) {
        int b = tid / NC, n = tid % NC;
        const float* h2f = a2;   // buffer 0
        float s = bfcs[n];
        #pragma unroll
        for (int j = 0; j < H2; ++j)
            s += h2f[j * AST + b] * wfcs[n * H2 + j];
        out[(size_t)(b0 + b) * NC + n] = s;
    }
}

extern "C" void kernel_launch(void* const* d_in, const int* in_sizes, int n_in,
                              void* d_out, int out_size)
{
    (void)in_sizes; (void)n_in; (void)out_size;
    const float* x     = (const float*)d_in[0];
    const float* w_ih1 = (const float*)d_in[1];
    const float* w_hh1 = (const float*)d_in[2];
    const float* b_ih1 = (const float*)d_in[3];
    const float* b_hh1 = (const float*)d_in[4];
    const float* w_ih2 = (const float*)d_in[5];
    const float* w_hh2 = (const float*)d_in[6];
    const float* b_ih2 = (const float*)d_in[7];
    const float* b_hh2 = (const float*)d_in[8];
    const float* w_fc  = (const float*)d_in[9];
    const float* b_fc  = (const float*)d_in[10];
    float* out = (float*)d_out;

    cudaFuncSetAttribute(lstm2_fused_kernel,
                         cudaFuncAttributeMaxDynamicSharedMemorySize, SMEM_BYTES);

    lstm2_fused_kernel<<<NBLOCKS, NTHREADS, SMEM_BYTES>>>(
        x, w_ih1, w_hh1, b_ih1, b_hh1,
        w_ih2, w_hh2, b_ih2, b_hh2,
        w_fc, b_fc, out);
}

// round 8
// speedup vs baseline: 1.4413x; 1.0409x over previous
#include <cuda_runtime.h>

// Problem constants
#define T_STEPS 256
#define I1 38
#define H1 50
#define H2 15
#define NC 14
#define K1 (I1 + H1)    // 88
#define K2 (H1 + H2)    // 65
#define BT 14           // batches per block (grid 296 = 2 x 148 SMs, balanced)
#define BTOT 4096
#define AST 20          // activation row stride (floats); 80B rows
#define NTHREADS 384
#define NBLOCKS 296

// Shared layout (floats):
//  W1s [K1][H1][4]  17600   (k, unit, gate i/f/g/o)
//  W2s [K2][H2][4]   3900
//  b1v [H1][4]        200
//  b2v [H2][4]         60
//  wfcs[NC*H2]        210
//  bfcs[NC]            14
//  a1  [2][K1][AST]  3520   rows 0..I1-1 = x_t, rows I1.. = h1
//  a2  [2][H2][AST]   600   h2 only
#define OFF_W1   0
#define OFF_W2   (OFF_W1 + K1 * H1 * 4)
#define OFF_B1   (OFF_W2 + K2 * H2 * 4)
#define OFF_B2   (OFF_B1 + H1 * 4)
#define OFF_WFC  (OFF_B2 + H2 * 4)
#define OFF_BFC  (OFF_WFC + NC * H2)
#define OFF_A1   (OFF_BFC + NC)
#define OFF_A2   (OFF_A1 + 2 * K1 * AST)
#define SMEM_FLOATS (OFF_A2 + 2 * H2 * AST)
#define SMEM_BYTES (SMEM_FLOATS * 4)   // ~106.5 KB -> 2 blocks/SM

#define NPF (NTHREADS - 288)   // 96 prefetch threads
#define PFN ((BT * I1 + NPF - 1) / NPF)   // max slots per prefetch thread (6)

__device__ __forceinline__ float fsig(float x) {
    return __fdividef(1.0f, 1.0f + __expf(-x));
}
__device__ __forceinline__ float ftanh_fast(float x) {
    return 1.0f - __fdividef(2.0f, 1.0f + __expf(2.0f * x));
}

__device__ __forceinline__ unsigned long long pack2(float w) {
    unsigned long long r;
    asm("mov.b64 %0, {%1, %1};" : "=l"(r) : "f"(w));
    return r;
}
__device__ __forceinline__ void ffma2(unsigned long long& d,
                                      unsigned long long a, unsigned long long b) {
    asm("fma.rn.f32x2 %0, %1, %2, %0;" : "+l"(d) : "l"(a), "l"(b));
}
__device__ __forceinline__ float2 unpk2(unsigned long long v) {
    float2 r;
    asm("mov.b64 {%0, %1}, %2;" : "=f"(r.x), "=f"(r.y) : "l"(v));
    return r;
}

extern __shared__ float smem[];

__global__ __launch_bounds__(NTHREADS, 2)
void lstm2_fused_kernel(const float* __restrict__ x,
                        const float* __restrict__ w_ih1, const float* __restrict__ w_hh1,
                        const float* __restrict__ b_ih1, const float* __restrict__ b_hh1,
                        const float* __restrict__ w_ih2, const float* __restrict__ w_hh2,
                        const float* __restrict__ b_ih2, const float* __restrict__ b_hh2,
                        const float* __restrict__ w_fc, const float* __restrict__ b_fc,
                        float* __restrict__ out)
{
    float* W1s  = smem + OFF_W1;
    float* W2s  = smem + OFF_W2;
    float* b1v  = smem + OFF_B1;
    float* b2v  = smem + OFF_B2;
    float* wfcs = smem + OFF_WFC;
    float* bfcs = smem + OFF_BFC;
    float* a1   = smem + OFF_A1;
    float* a2   = smem + OFF_A2;

    const int tid = threadIdx.x;
    const int b0  = blockIdx.x * BT;

    // ---- stage weights: (k, unit, gate) float4 groups ----
    for (int i = tid; i < K1 * H1 * 4; i += NTHREADS) {
        int k = i / (H1 * 4);
        int r = i - k * (H1 * 4);
        int uu = r >> 2, gi = r & 3;
        W1s[i] = (k < I1) ? w_ih1[(gi * H1 + uu) * I1 + k]
                          : w_hh1[(gi * H1 + uu) * H1 + (k - I1)];
    }
    for (int i = tid; i < K2 * H2 * 4; i += NTHREADS) {
        int k = i / (H2 * 4);
        int r = i - k * (H2 * 4);
        int uu = r >> 2, gi = r & 3;
        W2s[i] = (k < H1) ? w_ih2[(gi * H2 + uu) * H1 + k]
                          : w_hh2[(gi * H2 + uu) * H2 + (k - H1)];
    }
    for (int i = tid; i < H1 * 4; i += NTHREADS) {
        int uu = i >> 2, gi = i & 3;
        b1v[i] = b_ih1[gi * H1 + uu] + b_hh1[gi * H1 + uu];
    }
    for (int i = tid; i < H2 * 4; i += NTHREADS) {
        int uu = i >> 2, gi = i & 3;
        b2v[i] = b_ih2[gi * H2 + uu] + b_hh2[gi * H2 + uu];
    }
    for (int i = tid; i < NC * H2; i += NTHREADS) wfcs[i] = w_fc[i];
    for (int i = tid; i < NC; i += NTHREADS) bfcs[i] = b_fc[i];

    // ---- zero initial states (buffer 0); load x_0 (batch-clamped) ----
    for (int i = tid; i < H1 * AST; i += NTHREADS) a1[I1 * AST + i] = 0.0f;
    for (int i = tid; i < H2 * AST; i += NTHREADS) a2[i] = 0.0f;
    for (int i = tid; i < BT * I1; i += NTHREADS) {
        int b = i / I1, k = i % I1;
        int bg = b0 + b; if (bg > BTOT - 1) bg = BTOT - 1;
        a1[k * AST + b] = x[(size_t)bg * (T_STEPS * I1) + k];
    }

    // ---- thread role assignment ----
    // Phase 1: tids 0..199 dense; lanes 0-3 share one unit (weight dedup).
    const bool is_p1 = (tid < 200);
    const int u    = tid >> 2;
    const int quad = tid & 3;       // 0..3 (4 batch columns each)

    // Phase 2: tids 224..283 (60): unit u2, gate-pair gp, octet oct2
    const bool is_p2 = (tid >= 224) && (tid < 284);
    const int j2   = tid - 224;
    const int gp   = j2 & 1;        // 0: gates i,f ; 1: gates g,o
    const int rst  = j2 >> 1;       // 0..29
    const int u2   = rst % 15;
    const int oct2 = rst / 15;      // 0..1 (8 batch columns each)
    const unsigned p2mask = __ballot_sync(0xffffffffu, is_p2);

    // Prefetch: tids 288..383, precomputed slots (no div/mod in the loop)
    int pf_sts[PFN];     // smem offset k*AST+b
    int pf_gm[PFN];      // gmem element offset bg*T*I1 + k  (add t*I1 at use)
    int pf_n = 0;
    if (tid >= 288) {
        for (int j = 0; j < PFN; ++j) {
            int i = (tid - 288) + j * NPF;
            if (i < BT * I1) {
                int b = i / I1, k = i - b * I1;
                int bg = b0 + b; if (bg > BTOT - 1) bg = BTOT - 1;
                pf_sts[j] = k * AST + b;
                pf_gm[j]  = bg * (T_STEPS * I1) + k;
                pf_n = j + 1;
            }
        }
    }

    float c1r[4] = {0.f,0.f,0.f,0.f};
    float c2r[4] = {0.f,0.f,0.f,0.f};

    __syncthreads();

    for (int t = 0; t < T_STEPS; ++t) {
        const int p = t & 1, q = p ^ 1;
        float* a1p = a1 + p * (K1 * AST);
        float* a1q = a1 + q * (K1 * AST);
        float* a2p = a2 + p * (H2 * AST);
        float* a2q = a2 + q * (H2 * AST);

        // ===== Phase 1: layer-1, 200 dense threads, 1u x 4g x 4b each =====
        if (is_p1) {
            unsigned long long acc[4][2];
            {
                float4 bv = *reinterpret_cast<const float4*>(b1v + u * 4);
                acc[0][0] = acc[0][1] = pack2(bv.x);
                acc[1][0] = acc[1][1] = pack2(bv.y);
                acc[2][0] = acc[2][1] = pack2(bv.z);
                acc[3][0] = acc[3][1] = pack2(bv.w);
            }
            const float4* wp = reinterpret_cast<const float4*>(W1s) + u;
            const char* ap = reinterpret_cast<const char*>(a1p) + 16 * quad;
            #pragma unroll 8
            for (int k = 0; k < K1; ++k) {
                float4 wv = *wp; wp += H1;
                ulonglong2 av = *reinterpret_cast<const ulonglong2*>(ap);
                ap += AST * 4;
                unsigned long long w0 = pack2(wv.x);
                unsigned long long w1 = pack2(wv.y);
                unsigned long long w2 = pack2(wv.z);
                unsigned long long w3 = pack2(wv.w);
                ffma2(acc[0][0], w0, av.x); ffma2(acc[0][1], w0, av.y);
                ffma2(acc[1][0], w1, av.x); ffma2(acc[1][1], w1, av.y);
                ffma2(acc[2][0], w2, av.x); ffma2(acc[2][1], w2, av.y);
                ffma2(acc[3][0], w3, av.x); ffma2(acc[3][1], w3, av.y);
            }
            float hv[4];
            #pragma unroll
            for (int bp = 0; bp < 2; ++bp) {
                float2 vi = unpk2(acc[0][bp]);
                float2 vf = unpk2(acc[1][bp]);
                float2 vg = unpk2(acc[2][bp]);
                float2 vo = unpk2(acc[3][bp]);
                #pragma unroll
                for (int l = 0; l < 2; ++l) {
                    int bj = 2 * bp + l;
                    float ig = fsig(l ? vi.y : vi.x);
                    float fg = fsig(l ? vf.y : vf.x);
                    float gg = ftanh_fast(l ? vg.y : vg.x);
                    float og = fsig(l ? vo.y : vo.x);
                    float c  = fg * c1r[bj] + ig * gg;
                    c1r[bj]  = c;
                    hv[bj]   = og * ftanh_fast(c);
                }
            }
            *reinterpret_cast<float4*>(a1q + (I1 + u) * AST + 4 * quad) =
                make_float4(hv[0], hv[1], hv[2], hv[3]);
        } else if (tid >= 288) {
            // prefetch x_{t+1} via precomputed slots
            if (t + 1 < T_STEPS) {
                const int xoff = (t + 1) * I1;
                #pragma unroll
                for (int j = 0; j < PFN; ++j) {
                    if (j < pf_n) a1q[pf_sts[j]] = x[pf_gm[j] + xoff];
                }
            }
        }

        __syncthreads();   // the ONLY barrier per step

        // ===== Phase 2: layer-2, 60 threads (warps 7-8), 1u x 2g x 8b each =====
        // reads h1 directly from a1q h-rows (written this step), h2 from a2p
        if (is_p2) {
            unsigned long long P[4], Q[4];   // gp0: P=i,Q=f ; gp1: P=g,Q=o
            {
                float2 bb = *reinterpret_cast<const float2*>(b2v + u2 * 4 + gp * 2);
                unsigned long long bl = pack2(bb.x), bh = pack2(bb.y);
                #pragma unroll
                for (int bp = 0; bp < 4; ++bp) { P[bp] = bl; Q[bp] = bh; }
            }
            const unsigned long long* wp2 =
                reinterpret_cast<const unsigned long long*>(W2s) + u2 * 2 + gp;
            const char* ah = reinterpret_cast<const char*>(a1q + I1 * AST) + 32 * oct2; // h1 new
            #pragma unroll 5
            for (int k = 0; k < H1; ++k) {
                float2 wv = unpk2(*wp2); wp2 += H2 * 2;
                ulonglong2 aL = *reinterpret_cast<const ulonglong2*>(ah);
                ulonglong2 aH = *reinterpret_cast<const ulonglong2*>(ah + 16);
                ah += AST * 4;
                unsigned long long wl = pack2(wv.x), wh = pack2(wv.y);
                ffma2(P[0], wl, aL.x); ffma2(P[1], wl, aL.y);
                ffma2(P[2], wl, aH.x); ffma2(P[3], wl, aH.y);
                ffma2(Q[0], wh, aL.x); ffma2(Q[1], wh, aL.y);
                ffma2(Q[2], wh, aH.x); ffma2(Q[3], wh, aH.y);
            }
            const char* ah2 = reinterpret_cast<const char*>(a2p) + 32 * oct2;  // h2 old
            #pragma unroll
            for (int k = 0; k < H2; ++k) {
                float2 wv = unpk2(*wp2); wp2 += H2 * 2;
                ulonglong2 aL = *reinterpret_cast<const ulonglong2*>(ah2);
                ulonglong2 aH = *reinterpret_cast<const ulonglong2*>(ah2 + 16);
                ah2 += AST * 4;
                unsigned long long wl = pack2(wv.x), wh = pack2(wv.y);
                ffma2(P[0], wl, aL.x); ffma2(P[1], wl, aL.y);
                ffma2(P[2], wl, aH.x); ffma2(P[3], wl, aH.y);
                ffma2(Q[0], wh, aL.x); ffma2(Q[1], wh, aL.y);
                ffma2(Q[2], wh, aH.x); ffma2(Q[3], wh, aH.y);
            }
            // lane-pair exchange: even lane (gp0) keeps batch-pairs 0,1; odd keeps 2,3
            const bool evn = (gp == 0);
            unsigned long long GI[2], GF[2], GG[2], GO[2];
            #pragma unroll
            for (int jj = 0; jj < 2; ++jj) {
                unsigned long long sP = evn ? P[2 + jj] : P[jj];
                unsigned long long sQ = evn ? Q[2 + jj] : Q[jj];
                unsigned long long rP = __shfl_xor_sync(p2mask, sP, 1);
                unsigned long long rQ = __shfl_xor_sync(p2mask, sQ, 1);
                GI[jj] = evn ? P[jj]     : rP;
                GF[jj] = evn ? Q[jj]     : rQ;
                GG[jj] = evn ? rP        : P[2 + jj];
                GO[jj] = evn ? rQ        : Q[2 + jj];
            }
            float hv[4];
            #pragma unroll
            for (int jj = 0; jj < 2; ++jj) {
                float2 vi = unpk2(GI[jj]);
                float2 vf = unpk2(GF[jj]);
                float2 vg = unpk2(GG[jj]);
                float2 vo = unpk2(GO[jj]);
                #pragma unroll
                for (int l = 0; l < 2; ++l) {
                    int bj = 2 * jj + l;
                    float ig = fsig(l ? vi.y : vi.x);
                    float fg = fsig(l ? vf.y : vf.x);
                    float gg = ftanh_fast(l ? vg.y : vg.x);
                    float og = fsig(l ? vo.y : vo.x);
                    float c  = fg * c2r[bj] + ig * gg;
                    c2r[bj]  = c;
                    hv[bj]   = og * ftanh_fast(c);
                }
            }
            float* d = a2q + u2 * AST + oct2 * 8 + gp * 4;
            *reinterpret_cast<float4*>(d) = make_float4(hv[0], hv[1], hv[2], hv[3]);
        }
        // no barrier: next phase-1 touches disjoint rows/buffers
    }

    __syncthreads();
    // final h2 in buffer q of step 255: q = 0
    if (tid < BT * NC) {
        int b = tid / NC, n = tid % NC;
        int bg = b0 + b;
        if (bg < BTOT) {
            const float* h2f = a2;   // buffer 0
            float s = bfcs[n];
            #pragma unroll
            for (int j = 0; j < H2; ++j)
                s += h2f[j * AST + b] * wfcs[n * H2 + j];
            out[(size_t)bg * NC + n] = s;
        }
    }
}

extern "C" void kernel_launch(void* const* d_in, const int* in_sizes, int n_in,
                              void* d_out, int out_size)
{
    (void)in_sizes; (void)n_in; (void)out_size;
    const float* x     = (const float*)d_in[0];
    const float* w_ih1 = (const float*)d_in[1];
    const float* w_hh1 = (const float*)d_in[2];
    const float* b_ih1 = (const float*)d_in[3];
    const float* b_hh1 = (const float*)d_in[4];
    const float* w_ih2 = (const float*)d_in[5];
    const float* w_hh2 = (const float*)d_in[6];
    const float* b_ih2 = (const float*)d_in[7];
    const float* b_hh2 = (const float*)d_in[8];
    const float* w_fc  = (const float*)d_in[9];
    const float* b_fc  = (const float*)d_in[10];
    float* out = (float*)d_out;

    cudaFuncSetAttribute(lstm2_fused_kernel,
                         cudaFuncAttributeMaxDynamicSharedMemorySize, SMEM_BYTES);

    lstm2_fused_kernel<<<NBLOCKS, NTHREADS, SMEM_BYTES>>>(
        x, w_ih1, w_hh1, b_ih1, b_hh1,
        w_ih2, w_hh2, b_ih2, b_hh2,
        w_fc, b_fc, out);
}